// round 6
// baseline (speedup 1.0000x reference)
#include <cuda_runtime.h>
#include <cstdint>

#define TOK 4096   // B*S tokens
#define HD  1024
#define NE  8
#define FF  4096
#define TOPK 2

// ---------------- scratch (device globals) ----------------
__device__ int   g_counts[NE];
__device__ int   g_base[NE];
__device__ int   g_tok[NE][TOK];
__device__ int   g_sel_e[TOK * TOPK];
__device__ int   g_sel_s[TOK * TOPK];
__device__ float g_sel_w[TOK * TOPK];
__device__ float g_h[(size_t)TOK * TOPK * FF];   // pre-rounded tf32 bits (written by gemm1)
__device__ float g_y[(size_t)TOK * TOPK * HD];
// tf32-rounded copies of operands
__device__ float g_xt[(size_t)TOK * HD];
__device__ float g_w1t[(size_t)NE * HD * FF];
__device__ float g_w3t[(size_t)NE * HD * FF];
__device__ float g_w2t[(size_t)NE * FF * HD];

// ---------------- helpers ----------------
__device__ __forceinline__ uint32_t f2tf(float f) {
    uint32_t u; asm("cvt.rna.tf32.f32 %0, %1;" : "=r"(u) : "f"(f)); return u;
}
__device__ __forceinline__ uint32_t smem_u32(const void* p) {
    uint32_t a;
    asm("{ .reg .u64 t; cvta.to.shared.u64 t, %1; cvt.u32.u64 %0, t; }" : "=r"(a) : "l"(p));
    return a;
}
__device__ __forceinline__ void mma8(float* d, const uint32_t* a, const uint32_t* b) {
    asm volatile("mma.sync.aligned.m16n8k8.row.col.f32.tf32.tf32.f32 "
        "{%0,%1,%2,%3}, {%4,%5,%6,%7}, {%8,%9}, {%0,%1,%2,%3};"
        : "+f"(d[0]), "+f"(d[1]), "+f"(d[2]), "+f"(d[3])
        : "r"(a[0]), "r"(a[1]), "r"(a[2]), "r"(a[3]), "r"(b[0]), "r"(b[1]));
}
#define CP16(dst32, src) \
    asm volatile("cp.async.cg.shared.global [%0], [%1], 16;" :: "r"(dst32), "l"(src) : "memory")
#define CP_COMMIT() asm volatile("cp.async.commit_group;" ::: "memory")
#define CP_WAIT0()  asm volatile("cp.async.wait_group 0;" ::: "memory")
#define CP_WAIT1()  asm volatile("cp.async.wait_group 1;" ::: "memory")

// ---------------- prep: tf32-round a buffer (2 float4 per thread) ----------------
__global__ void round_tf32_kernel(const float4* __restrict__ src,
                                  float4* __restrict__ dst, int n4) {
    int i = (blockIdx.x * blockDim.x + threadIdx.x) * 2;
    if (i + 1 < n4) {
        float4 v0 = src[i];
        float4 v1 = src[i + 1];
        float4 o0, o1;
        o0.x = __uint_as_float(f2tf(v0.x)); o0.y = __uint_as_float(f2tf(v0.y));
        o0.z = __uint_as_float(f2tf(v0.z)); o0.w = __uint_as_float(f2tf(v0.w));
        o1.x = __uint_as_float(f2tf(v1.x)); o1.y = __uint_as_float(f2tf(v1.y));
        o1.z = __uint_as_float(f2tf(v1.z)); o1.w = __uint_as_float(f2tf(v1.w));
        dst[i] = o0;
        dst[i + 1] = o1;
    } else if (i < n4) {
        float4 v = src[i];
        float4 o;
        o.x = __uint_as_float(f2tf(v.x)); o.y = __uint_as_float(f2tf(v.y));
        o.z = __uint_as_float(f2tf(v.z)); o.w = __uint_as_float(f2tf(v.w));
        dst[i] = o;
    }
}

// ---------------- kernel 0: zero counters ----------------
__global__ void zero_counts_kernel() {
    if (threadIdx.x < NE) g_counts[threadIdx.x] = 0;
}

// ---------------- kernel 1: routing ----------------
__global__ void routing_kernel(const float* __restrict__ x,
                               const float* __restrict__ Wg,
                               const float* __restrict__ bg) {
    const int t = blockIdx.x, tid = threadIdx.x, wid = tid >> 5, lid = tid & 31;
    __shared__ float s_logit[NE];
    const float* xt = x + (size_t)t * HD;
    float acc = 0.f;
    for (int h = lid; h < HD; h += 32) acc += xt[h] * Wg[h * NE + wid];
    #pragma unroll
    for (int o = 16; o > 0; o >>= 1) acc += __shfl_down_sync(0xFFFFFFFFu, acc, o);
    if (lid == 0) s_logit[wid] = acc + bg[wid];
    __syncthreads();
    if (tid == 0) {
        float l[NE];
        #pragma unroll
        for (int e = 0; e < NE; e++) l[e] = s_logit[e];
        int i0 = 0;
        #pragma unroll
        for (int e = 1; e < NE; e++) if (l[e] > l[i0]) i0 = e;
        int i1 = (i0 == 0) ? 1 : 0;
        #pragma unroll
        for (int e = 0; e < NE; e++) if (e != i0 && l[e] > l[i1]) i1 = e;
        float w1 = __expf(l[i1] - l[i0]);
        float inv = 1.f / (1.f + w1);
        int s0 = atomicAdd(&g_counts[i0], 1);
        int s1 = atomicAdd(&g_counts[i1], 1);
        g_tok[i0][s0] = t;  g_tok[i1][s1] = t;
        g_sel_e[t*2+0] = i0; g_sel_s[t*2+0] = s0; g_sel_w[t*2+0] = inv;
        g_sel_e[t*2+1] = i1; g_sel_s[t*2+1] = s1; g_sel_w[t*2+1] = w1 * inv;
    }
}

// ---------------- kernel 2: bases ----------------
__global__ void bases_kernel() {
    if (threadIdx.x == 0) {
        int b = 0;
        #pragma unroll
        for (int e = 0; e < NE; e++) { g_base[e] = b; b += g_counts[e]; }
    }
}

// ======================= GEMM1 =======================
// CTA 128M x 64N fused (W1,W3), BK=32, 3-stage cp.async, 1 sync/chunk, 2 CTA/SM.
// Pads: A row 36 words (bank 4g+tig), B row 72 words (bank 8tig+g) — conflict-free.
// smem: toks[128] @0 | A[3][128][36] @512 | B1[3][32][72] @55808 | B3[3][32][72] @83456
#define G1_A_OFF  512
#define G1_B1_OFF 55808
#define G1_B3_OFF 83456
#define G1_SMEM   111104
#define G1_A_STG  18432
#define G1_B_STG  9216

__device__ __forceinline__ void g1_load_stage(uint32_t sb, int s, int k0,
                                              const int* toks,
                                              const float* __restrict__ W1t,
                                              const float* __restrict__ W3t,
                                              int n0, int tid) {
    const uint32_t aB = sb + G1_A_OFF + s * G1_A_STG;
    #pragma unroll
    for (int q = 0; q < 4; q++) {
        int id = q * 256 + tid, row = id >> 3, c4 = id & 7;
        CP16(aB + row * 144 + c4 * 16, g_xt + (size_t)toks[row] * HD + k0 + c4 * 4);
    }
    const uint32_t b1B = sb + G1_B1_OFF + s * G1_B_STG;
    const uint32_t b3B = sb + G1_B3_OFF + s * G1_B_STG;
    #pragma unroll
    for (int q = 0; q < 2; q++) {
        int id = q * 256 + tid, kl = id >> 4, nq = id & 15;
        size_t off = (size_t)(k0 + kl) * FF + n0 + nq * 4;
        CP16(b1B + kl * 288 + nq * 16, W1t + off);
        CP16(b3B + kl * 288 + nq * 16, W3t + off);
    }
    CP_COMMIT();
}

__global__ __launch_bounds__(256, 2) void gemm1_mma() {
    const int e  = blockIdx.z;
    const int n  = g_counts[e];
    const int m0 = blockIdx.y * 128;
    if (m0 >= n) return;
    const int n0   = blockIdx.x * 64;
    const int base = g_base[e];

    extern __shared__ char dynsmem[];
    const uint32_t sb = smem_u32(dynsmem);
    int* toks = (int*)dynsmem;
    const uint32_t* As  = (const uint32_t*)(dynsmem + G1_A_OFF);
    const uint32_t* B1s = (const uint32_t*)(dynsmem + G1_B1_OFF);
    const uint32_t* B3s = (const uint32_t*)(dynsmem + G1_B3_OFF);

    const int tid = threadIdx.x, wid = tid >> 5, lane = tid & 31;
    const int g = lane >> 2, tig = lane & 3;
    const int wm = wid >> 1, wn = wid & 1;

    if (tid < 128) { int r = m0 + tid; toks[tid] = g_tok[e][r < n ? r : n - 1]; }
    __syncthreads();

    const float* __restrict__ W1t = g_w1t + (size_t)e * HD * FF;
    const float* __restrict__ W3t = g_w3t + (size_t)e * HD * FF;

    float cg[2][4][4] = {};
    float cu[2][4][4] = {};

    // prologue: stages 0,1
    g1_load_stage(sb, 0, 0, toks, W1t, W3t, n0, tid);
    g1_load_stage(sb, 1, 32, toks, W1t, W3t, n0, tid);

    const int NC = HD / 32;
    for (int c = 0; c < NC; c++) {
        if (c + 1 < NC) { CP_WAIT1(); } else { CP_WAIT0(); }
        __syncthreads();
        if (c + 2 < NC)
            g1_load_stage(sb, (c + 2) % 3, (c + 2) * 32, toks, W1t, W3t, n0, tid);

        const int s = c % 3;
        const uint32_t* Ap  = As  + s * 4608;   // 128*36
        const uint32_t* B1p = B1s + s * 2304;   // 32*72
        const uint32_t* B3p = B3s + s * 2304;

        #pragma unroll
        for (int ks = 0; ks < 4; ks++) {
            const int kk = ks * 8;
            uint32_t a[2][4];
            #pragma unroll
            for (int mt = 0; mt < 2; mt++) {
                const int rb = wm * 32 + mt * 16;
                a[mt][0] = Ap[(rb + g) * 36 + kk + tig];
                a[mt][1] = Ap[(rb + g + 8) * 36 + kk + tig];
                a[mt][2] = Ap[(rb + g) * 36 + kk + tig + 4];
                a[mt][3] = Ap[(rb + g + 8) * 36 + kk + tig + 4];
            }
            #pragma unroll
            for (int nt = 0; nt < 4; nt++) {
                const int nb = wn * 32 + nt * 8;
                uint32_t b1[2] = { B1p[(kk + tig) * 72 + nb + g], B1p[(kk + tig + 4) * 72 + nb + g] };
                uint32_t b3[2] = { B3p[(kk + tig) * 72 + nb + g], B3p[(kk + tig + 4) * 72 + nb + g] };
                #pragma unroll
                for (int mt = 0; mt < 2; mt++) {
                    mma8(cg[mt][nt], a[mt], b1);
                    mma8(cu[mt][nt], a[mt], b3);
                }
            }
        }
    }

    // epilogue: h = silu(g) * u, pre-rounded to tf32 for gemm2
    #pragma unroll
    for (int mt = 0; mt < 2; mt++) {
        #pragma unroll
        for (int half = 0; half < 2; half++) {
            const int r = m0 + wm * 32 + mt * 16 + g + half * 8;
            if (r >= n) continue;
            float* hp = g_h + (size_t)(base + r) * FF + n0 + wn * 32 + 2 * tig;
            #pragma unroll
            for (int nt = 0; nt < 4; nt++) {
                float g0 = cg[mt][nt][half * 2 + 0], g1 = cg[mt][nt][half * 2 + 1];
                float u0 = cu[mt][nt][half * 2 + 0], u1 = cu[mt][nt][half * 2 + 1];
                float2 o;
                o.x = __uint_as_float(f2tf((g0 / (1.f + __expf(-g0))) * u0));
                o.y = __uint_as_float(f2tf((g1 / (1.f + __expf(-g1))) * u1));
                *(float2*)(hp + nt * 8) = o;
            }
        }
    }
}

// ======================= GEMM2 =======================
// CTA 128M x 128N, BK=32, 3-stage cp.async, 1 sync/chunk, 2 CTA/SM.
// Pads: A 36 words, B 136 words — conflict-free.
// smem: A[3][128][36] @0 | B[3][32][136] @55296
#define G2_B_OFF 55296
#define G2_SMEM  107520
#define G2_A_STG 18432
#define G2_B_STG 17408

__device__ __forceinline__ void g2_load_stage(uint32_t sb, int s, int k0,
                                              const float* __restrict__ W2t,
                                              int base, int m0, int n, int n0, int tid) {
    const uint32_t aB = sb + s * G2_A_STG;
    #pragma unroll
    for (int q = 0; q < 4; q++) {
        int id = q * 256 + tid, row = id >> 3, c4 = id & 7;
        int rg = m0 + row; if (rg >= n) rg = n - 1;
        CP16(aB + row * 144 + c4 * 16, g_h + (size_t)(base + rg) * FF + k0 + c4 * 4);
    }
    const uint32_t bB = sb + G2_B_OFF + s * G2_B_STG;
    #pragma unroll
    for (int q = 0; q < 4; q++) {
        int id = q * 256 + tid, kl = id >> 5, nq = id & 31;
        CP16(bB + kl * 544 + nq * 16, W2t + (size_t)(k0 + kl) * HD + n0 + nq * 4);
    }
    CP_COMMIT();
}

__global__ __launch_bounds__(256, 2) void gemm2_mma() {
    const int e  = blockIdx.z;
    const int n  = g_counts[e];
    const int m0 = blockIdx.y * 128;
    if (m0 >= n) return;
    const int n0   = blockIdx.x * 128;
    const int base = g_base[e];

    extern __shared__ char dynsmem[];
    const uint32_t sb = smem_u32(dynsmem);
    const uint32_t* As = (const uint32_t*)dynsmem;
    const uint32_t* Bs = (const uint32_t*)(dynsmem + G2_B_OFF);

    const int tid = threadIdx.x, wid = tid >> 5, lane = tid & 31;
    const int g = lane >> 2, tig = lane & 3;
    const int wm = wid >> 1, wn = wid & 1;

    const float* __restrict__ W2t = g_w2t + (size_t)e * FF * HD;

    float cacc[2][8][4] = {};

    g2_load_stage(sb, 0, 0, W2t, base, m0, n, n0, tid);
    g2_load_stage(sb, 1, 32, W2t, base, m0, n, n0, tid);

    const int NC = FF / 32;
    for (int c = 0; c < NC; c++) {
        if (c + 1 < NC) { CP_WAIT1(); } else { CP_WAIT0(); }
        __syncthreads();
        if (c + 2 < NC)
            g2_load_stage(sb, (c + 2) % 3, (c + 2) * 32, W2t, base, m0, n, n0, tid);

        const int s = c % 3;
        const uint32_t* Ap = As + s * 4608;   // 128*36
        const uint32_t* Bp = Bs + s * 4352;   // 32*136

        #pragma unroll
        for (int ks = 0; ks < 4; ks++) {
            const int kk = ks * 8;
            uint32_t a[2][4];
            #pragma unroll
            for (int mt = 0; mt < 2; mt++) {
                const int rb = wm * 32 + mt * 16;
                a[mt][0] = Ap[(rb + g) * 36 + kk + tig];
                a[mt][1] = Ap[(rb + g + 8) * 36 + kk + tig];
                a[mt][2] = Ap[(rb + g) * 36 + kk + tig + 4];
                a[mt][3] = Ap[(rb + g + 8) * 36 + kk + tig + 4];
            }
            #pragma unroll
            for (int nt = 0; nt < 8; nt++) {
                const int nb = wn * 64 + nt * 8;
                uint32_t b[2] = { Bp[(kk + tig) * 136 + nb + g], Bp[(kk + tig + 4) * 136 + nb + g] };
                #pragma unroll
                for (int mt = 0; mt < 2; mt++) mma8(cacc[mt][nt], a[mt], b);
            }
        }
    }

    #pragma unroll
    for (int mt = 0; mt < 2; mt++) {
        #pragma unroll
        for (int half = 0; half < 2; half++) {
            const int r = m0 + wm * 32 + mt * 16 + g + half * 8;
            if (r >= n) continue;
            float* yp = g_y + (size_t)(base + r) * HD + n0 + wn * 64 + 2 * tig;
            #pragma unroll
            for (int nt = 0; nt < 8; nt++) {
                float2 o;
                o.x = cacc[mt][nt][half * 2 + 0];
                o.y = cacc[mt][nt][half * 2 + 1];
                *(float2*)(yp + nt * 8) = o;
            }
        }
    }
}

// ---------------- combine ----------------
__global__ void combine_kernel(float* __restrict__ out) {
    const int idx = blockIdx.x * blockDim.x + threadIdx.x;
    const int t = idx / (HD / 4);
    const int c4 = idx % (HD / 4);
    float4 acc = make_float4(0.f, 0.f, 0.f, 0.f);
    #pragma unroll
    for (int k = 0; k < TOPK; k++) {
        int e = g_sel_e[t * 2 + k];
        int s = g_sel_s[t * 2 + k];
        float w = g_sel_w[t * 2 + k];
        const float4 v = *(const float4*)(g_y + (size_t)(g_base[e] + s) * HD + c4 * 4);
        acc.x += w * v.x; acc.y += w * v.y; acc.z += w * v.z; acc.w += w * v.w;
    }
    *(float4*)(out + (size_t)t * HD + c4 * 4) = acc;
}

// ---------------- launcher ----------------
extern "C" void kernel_launch(void* const* d_in, const int* in_sizes, int n_in,
                              void* d_out, int out_size) {
    const float* x  = (const float*)d_in[0];
    const float* Wg = (const float*)d_in[1];
    const float* bg = (const float*)d_in[2];
    const float* W1 = (const float*)d_in[3];
    const float* W3 = (const float*)d_in[4];
    const float* W2 = (const float*)d_in[5];
    float* out = (float*)d_out;

    cudaFuncSetAttribute(gemm1_mma, cudaFuncAttributeMaxDynamicSharedMemorySize, G1_SMEM);
    cudaFuncSetAttribute(gemm2_mma, cudaFuncAttributeMaxDynamicSharedMemorySize, G2_SMEM);

    float *xt_p, *w1t_p, *w3t_p, *w2t_p;
    cudaGetSymbolAddress((void**)&xt_p,  g_xt);
    cudaGetSymbolAddress((void**)&w1t_p, g_w1t);
    cudaGetSymbolAddress((void**)&w3t_p, g_w3t);
    cudaGetSymbolAddress((void**)&w2t_p, g_w2t);

    const int wN4 = NE * HD * FF / 4;
    const int xN4 = TOK * HD / 4;

    round_tf32_kernel<<<(xN4 / 2 + 255) / 256, 256>>>((const float4*)x,  (float4*)xt_p,  xN4);
    round_tf32_kernel<<<(wN4 / 2 + 255) / 256, 256>>>((const float4*)W1, (float4*)w1t_p, wN4);
    round_tf32_kernel<<<(wN4 / 2 + 255) / 256, 256>>>((const float4*)W3, (float4*)w3t_p, wN4);
    round_tf32_kernel<<<(wN4 / 2 + 255) / 256, 256>>>((const float4*)W2, (float4*)w2t_p, wN4);

    zero_counts_kernel<<<1, 32>>>();
    routing_kernel<<<TOK, 256>>>(x, Wg, bg);
    bases_kernel<<<1, 1>>>();
    gemm1_mma<<<dim3(FF / 64, TOK / 128, NE), 256, G1_SMEM>>>();
    gemm2_mma<<<dim3(HD / 128, TOK / 128, NE), 256, G2_SMEM>>>();
    combine_kernel<<<(TOK * (HD / 4)) / 256, 256>>>(out);
}